// round 5
// baseline (speedup 1.0000x reference)
#include <cuda_runtime.h>
#include <cstdint>
#include <math.h>

// ---------------- problem constants ----------------
#define M_TOK 512
#define H_DIM 2048
#define E_NUM 8
#define I_DIM 5632
#define P_NUM 1024   // M_TOK * top_k

// ---------------- gemm tiling ----------------
#define BM 128
#define BN 128
#define BK 16
#define PAD_A 20     // As row stride (floats): conflict-free for frag loads, 16B-aligned rows
#define PAD_B 136    // Bs row stride (floats): conflict-free for frag loads, 16B-aligned rows

// ---------------- scratch (device globals: no allocation allowed) ----------------
__device__ __align__(16) float g_gu[(size_t)P_NUM * 2 * I_DIM];  // 46 MB gate_up
__device__ __align__(16) float g_h [(size_t)P_NUM * I_DIM];      // 23 MB silu(g)*u
__device__ __align__(16) float g_dn[(size_t)P_NUM * H_DIM];      //  8 MB down proj per pair
__device__ int   g_cnt[E_NUM];
__device__ int   g_list[E_NUM * M_TOK];   // pair ids per expert
__device__ float g_pw[P_NUM];             // routing weight per pair (p = 2*m + k)

// ---------------- helpers ----------------
__device__ __forceinline__ uint32_t f2tf(float f) {
    uint32_t u;
    asm("cvt.rna.tf32.f32 %0, %1;" : "=r"(u) : "f"(f));
    return u;
}

__device__ __forceinline__ void mma_tf32(float* c, const uint32_t* a, const uint32_t* b) {
    asm volatile(
        "mma.sync.aligned.m16n8k8.row.col.f32.tf32.tf32.f32 "
        "{%0,%1,%2,%3}, {%4,%5,%6,%7}, {%8,%9}, {%0,%1,%2,%3};\n"
        : "+f"(c[0]), "+f"(c[1]), "+f"(c[2]), "+f"(c[3])
        : "r"(a[0]), "r"(a[1]), "r"(a[2]), "r"(a[3]), "r"(b[0]), "r"(b[1]));
}

__device__ __forceinline__ void cp_async16(uint32_t smem, const void* gmem, int src_bytes) {
    asm volatile("cp.async.ca.shared.global [%0], [%1], 16, %2;\n"
                 :: "r"(smem), "l"(gmem), "r"(src_bytes) : "memory");
}
__device__ __forceinline__ void cp_commit() {
    asm volatile("cp.async.commit_group;\n" ::: "memory");
}

// ---------------- reset ----------------
__global__ void reset_kernel() {
    if (threadIdx.x < E_NUM) g_cnt[threadIdx.x] = 0;
}

// ---------------- router: logits -> softmax -> top2 -> renorm -> lists ----------------
__global__ void router_kernel(const float* __restrict__ x, const float* __restrict__ wg) {
    int warp = (blockIdx.x * blockDim.x + threadIdx.x) >> 5;
    int lane = threadIdx.x & 31;
    if (warp >= M_TOK) return;
    const float* xr = x + (long long)warp * H_DIM;
    float acc[E_NUM];
#pragma unroll
    for (int e = 0; e < E_NUM; e++) acc[e] = 0.f;
    for (int h = lane; h < H_DIM; h += 32) {
        float xv = xr[h];
        const float4* wr = (const float4*)(wg + (long long)h * E_NUM);
        float4 w0 = wr[0], w1 = wr[1];
        acc[0] += xv * w0.x; acc[1] += xv * w0.y; acc[2] += xv * w0.z; acc[3] += xv * w0.w;
        acc[4] += xv * w1.x; acc[5] += xv * w1.y; acc[6] += xv * w1.z; acc[7] += xv * w1.w;
    }
#pragma unroll
    for (int e = 0; e < E_NUM; e++)
#pragma unroll
        for (int o = 16; o > 0; o >>= 1)
            acc[e] += __shfl_xor_sync(0xffffffffu, acc[e], o);
    if (lane == 0) {
        float mx = acc[0];
#pragma unroll
        for (int e = 1; e < E_NUM; e++) mx = fmaxf(mx, acc[e]);
        float p[E_NUM];
#pragma unroll
        for (int e = 0; e < E_NUM; e++) p[e] = expf(acc[e] - mx);
        int i0 = 0;
#pragma unroll
        for (int e = 1; e < E_NUM; e++) if (p[e] > p[i0]) i0 = e;
        int i1 = (i0 == 0) ? 1 : 0;
#pragma unroll
        for (int e = 0; e < E_NUM; e++) { if (e == i0 || e == i1) continue; if (p[e] > p[i1]) i1 = e; }
        float denom = p[i0] + p[i1];
        int m = warp;
        g_pw[2 * m + 0] = p[i0] / denom;
        g_pw[2 * m + 1] = p[i1] / denom;
        int s0 = atomicAdd(&g_cnt[i0], 1); g_list[i0 * M_TOK + s0] = 2 * m + 0;
        int s1 = atomicAdd(&g_cnt[i1], 1); g_list[i1 * M_TOK + s1] = 2 * m + 1;
    }
}

// ---------------- grouped GEMM (tf32 mma.sync m16n8k8) ----------------
// MODE 1: A = x (row = pair>>1), W = w1[e] (K=H, N=2I), C = g_gu (row = pair)
// MODE 2: A = g_h (row = pair),  W = w2[e] (K=I, N=H),  C = g_dn (row = pair)
template<int MODE>
__global__ void __launch_bounds__(256) grouped_gemm_kernel(
    const float* __restrict__ Aext, const float* __restrict__ Wbase,
    int K, int N, int ldA, int ldC)
{
    const float* Asrc = (MODE == 1) ? Aext : (const float*)g_h;
    float* C = (MODE == 1) ? g_gu : g_dn;

    int e = blockIdx.z;
    int cnt = g_cnt[e];
    int row0 = blockIdx.x * BM;       // m-tile fastest -> concurrent blocks share W tile in L2
    if (row0 >= cnt) return;
    int n0 = blockIdx.y * BN;
    const float* W = Wbase + (long long)e * K * N;

    __shared__ float As[2][BM * PAD_A];
    __shared__ float Bs[2][BK * PAD_B];

    int tid = threadIdx.x;

    const float* aptr[2]; int avalid[2];
    const float* bptr[2];
    uint32_t sA[2], sB[2];
#pragma unroll
    for (int j = 0; j < 2; j++) {
        int idx = tid + j * 256;
        int r = idx >> 2, seg = idx & 3;          // A: 128 rows x 4 x 16B
        int gr = row0 + r;
        int srow = 0;
        if (gr < cnt) {
            int p = g_list[e * M_TOK + gr];
            srow = (MODE == 1) ? (p >> 1) : p;
            avalid[j] = 16;
        } else {
            avalid[j] = 0;                        // cp.async ZFILL
        }
        aptr[j] = Asrc + (long long)srow * ldA + seg * 4;
        sA[j] = (uint32_t)__cvta_generic_to_shared(&As[0][r * PAD_A + seg * 4]);

        int kr = idx >> 5, bseg = idx & 31;       // B: 16 rows x 32 x 16B
        bptr[j] = W + (long long)kr * N + n0 + bseg * 4;
        sB[j] = (uint32_t)__cvta_generic_to_shared(&Bs[0][kr * PAD_B + bseg * 4]);
    }
    const uint32_t stA = BM * PAD_A * 4;
    const uint32_t stB = BK * PAD_B * 4;

    float c[4][4][4];
#pragma unroll
    for (int i = 0; i < 4; i++)
#pragma unroll
        for (int j = 0; j < 4; j++)
#pragma unroll
            for (int k = 0; k < 4; k++) c[i][j][k] = 0.f;

    int warp = tid >> 5, lane = tid & 31;
    int wm = warp >> 2, wn = warp & 3;            // 2 m-warps x 4 n-warps; warp tile 64x32
    int g = lane >> 2, t = lane & 3;

    int nK = K / BK;

    // prologue: stage 0
#pragma unroll
    for (int j = 0; j < 2; j++) cp_async16(sA[j], aptr[j], avalid[j]);
#pragma unroll
    for (int j = 0; j < 2; j++) cp_async16(sB[j], bptr[j], 16);
    cp_commit();

    for (int kt = 0; kt < nK; kt++) {
        if (kt + 1 < nK) {
            int s1 = (kt + 1) & 1;
            long long k0 = (long long)(kt + 1) * BK;
#pragma unroll
            for (int j = 0; j < 2; j++) cp_async16(sA[j] + s1 * stA, aptr[j] + k0, avalid[j]);
#pragma unroll
            for (int j = 0; j < 2; j++) cp_async16(sB[j] + s1 * stB, bptr[j] + k0 * N, 16);
            cp_commit();
            asm volatile("cp.async.wait_group 1;\n" ::: "memory");
        } else {
            asm volatile("cp.async.wait_group 0;\n" ::: "memory");
        }
        __syncthreads();

        int s = kt & 1;
        const float* as = As[s];
        const float* bs = Bs[s];
#pragma unroll
        for (int kk = 0; kk < BK; kk += 8) {
            uint32_t a[4][4];
#pragma unroll
            for (int mi = 0; mi < 4; mi++) {
                int mr = wm * 64 + mi * 16 + g;
                a[mi][0] = f2tf(as[mr * PAD_A + kk + t]);
                a[mi][1] = f2tf(as[(mr + 8) * PAD_A + kk + t]);
                a[mi][2] = f2tf(as[mr * PAD_A + kk + t + 4]);
                a[mi][3] = f2tf(as[(mr + 8) * PAD_A + kk + t + 4]);
            }
            uint32_t b[4][2];
#pragma unroll
            for (int ni = 0; ni < 4; ni++) {
                int nc = wn * 32 + ni * 8 + g;
                b[ni][0] = f2tf(bs[(kk + t) * PAD_B + nc]);
                b[ni][1] = f2tf(bs[(kk + t + 4) * PAD_B + nc]);
            }
#pragma unroll
            for (int mi = 0; mi < 4; mi++)
#pragma unroll
                for (int ni = 0; ni < 4; ni++)
                    mma_tf32(c[mi][ni], a[mi], b[ni]);
        }
        __syncthreads();
    }

    // writeback (skip padded rows)
#pragma unroll
    for (int mi = 0; mi < 4; mi++) {
#pragma unroll
        for (int half = 0; half < 2; half++) {
            int r = wm * 64 + mi * 16 + g + half * 8;
            int gr = row0 + r;
            if (gr < cnt) {
                int p = g_list[e * M_TOK + gr];
                float* dst = C + (long long)p * ldC + n0;
#pragma unroll
                for (int ni = 0; ni < 4; ni++) {
                    float2 v;
                    v.x = c[mi][ni][half * 2 + 0];
                    v.y = c[mi][ni][half * 2 + 1];
                    *(float2*)(dst + wn * 32 + ni * 8 + 2 * t) = v;
                }
            }
        }
    }
}

// ---------------- silu(g) * u ----------------
__global__ void silu_mul_kernel() {
    const int I4 = I_DIM / 4;
    long long idx = (long long)blockIdx.x * blockDim.x + threadIdx.x; // exactly P_NUM*I4 threads
    long long p = idx / I4;
    int i4 = (int)(idx % I4);
    const float* gp = g_gu + p * (2 * I_DIM);
    float4 gv = *(const float4*)(gp + i4 * 4);
    float4 uv = *(const float4*)(gp + I_DIM + i4 * 4);
    float4 h;
    h.x = gv.x / (1.f + expf(-gv.x)) * uv.x;
    h.y = gv.y / (1.f + expf(-gv.y)) * uv.y;
    h.z = gv.z / (1.f + expf(-gv.z)) * uv.z;
    h.w = gv.w / (1.f + expf(-gv.w)) * uv.w;
    *(float4*)(g_h + p * I_DIM + i4 * 4) = h;
}

// ---------------- combine: out[m] = w0*down[2m] + w1*down[2m+1] ----------------
__global__ void combine_kernel(float* __restrict__ out) {
    const int H4 = H_DIM / 4;
    int idx = blockIdx.x * blockDim.x + threadIdx.x;  // exactly M_TOK*H4 threads
    int m = idx / H4;
    int h4 = idx % H4;
    float w0 = g_pw[2 * m + 0];
    float w1 = g_pw[2 * m + 1];
    float4 d0 = *(const float4*)(g_dn + (long long)(2 * m + 0) * H_DIM + h4 * 4);
    float4 d1 = *(const float4*)(g_dn + (long long)(2 * m + 1) * H_DIM + h4 * 4);
    float4 o;
    o.x = w0 * d0.x + w1 * d1.x;
    o.y = w0 * d0.y + w1 * d1.y;
    o.z = w0 * d0.z + w1 * d1.z;
    o.w = w0 * d0.w + w1 * d1.w;
    *(float4*)(out + (long long)m * H_DIM + h4 * 4) = o;
}

// ---------------- launcher ----------------
extern "C" void kernel_launch(void* const* d_in, const int* in_sizes, int n_in,
                              void* d_out, int out_size) {
    const float* x  = (const float*)d_in[0];   // [1,512,2048]
    const float* wg = (const float*)d_in[1];   // [2048,8]
    const float* w1 = (const float*)d_in[2];   // [8,2048,11264]
    const float* w2 = (const float*)d_in[3];   // [8,5632,2048]
    float* out = (float*)d_out;                // [1,512,2048]
    (void)in_sizes; (void)n_in; (void)out_size;

    reset_kernel<<<1, 32>>>();
    router_kernel<<<M_TOK / 8, 256>>>(x, wg);  // 1 warp / token

    dim3 grid1(M_TOK / BM, (2 * I_DIM) / BN, E_NUM);  // (4, 88, 8)
    grouped_gemm_kernel<1><<<grid1, 256>>>(x, w1, H_DIM, 2 * I_DIM, H_DIM, 2 * I_DIM);

    silu_mul_kernel<<<(P_NUM * (I_DIM / 4)) / 256, 256>>>();  // 5632 blocks, exact cover

    dim3 grid2(M_TOK / BM, H_DIM / BN, E_NUM);        // (4, 16, 8)
    grouped_gemm_kernel<2><<<grid2, 256>>>(x /*unused*/, w2, I_DIM, H_DIM, I_DIM, H_DIM);

    combine_kernel<<<(M_TOK * (H_DIM / 4)) / 256, 256>>>(out);
}

// round 6
// speedup vs baseline: 1.0414x; 1.0414x over previous
#include <cuda_runtime.h>
#include <cuda_fp16.h>
#include <cstdint>
#include <math.h>

// ---------------- problem constants ----------------
#define M_TOK 512
#define H_DIM 2048
#define E_NUM 8
#define I_DIM 5632
#define P_NUM 1024   // M_TOK * top_k

// ---------------- gemm tiling ----------------
#define BM 128
#define BN 128
#define BK 32
#define LDA 40    // As row stride in halves (80B) -> conflict-free ldmatrix.x4
#define LDB 136   // Bs row stride in halves (272B) -> conflict-free ldmatrix.x2.trans

// ---------------- scratch (device globals: no allocation allowed) ----------------
__device__ __align__(16) float g_gu[(size_t)P_NUM * 2 * I_DIM];  // 46 MB gate_up
__device__ __align__(16) float g_h [(size_t)P_NUM * I_DIM];      // 23 MB silu(g)*u
__device__ __align__(16) float g_dn[(size_t)P_NUM * H_DIM];      //  8 MB down proj per pair
__device__ int   g_cnt[E_NUM];
__device__ int   g_list[E_NUM * M_TOK];   // pair ids per expert
__device__ float g_pw[P_NUM];             // routing weight per pair (p = 2*m + k)

// ---------------- helpers ----------------
__device__ __forceinline__ uint32_t pack2(float x, float y) {
    __half2 h = __floats2half2_rn(x, y);   // x -> low half, y -> high half
    return *reinterpret_cast<uint32_t*>(&h);
}

__device__ __forceinline__ void mma16816(float* c, const uint32_t* a, const uint32_t* b) {
    asm volatile(
        "mma.sync.aligned.m16n8k16.row.col.f32.f16.f16.f32 "
        "{%0,%1,%2,%3}, {%4,%5,%6,%7}, {%8,%9}, {%0,%1,%2,%3};\n"
        : "+f"(c[0]), "+f"(c[1]), "+f"(c[2]), "+f"(c[3])
        : "r"(a[0]), "r"(a[1]), "r"(a[2]), "r"(a[3]), "r"(b[0]), "r"(b[1]));
}

__device__ __forceinline__ uint32_t sptr(const void* p) {
    return (uint32_t)__cvta_generic_to_shared(p);
}

// ---------------- reset ----------------
__global__ void reset_kernel() {
    if (threadIdx.x < E_NUM) g_cnt[threadIdx.x] = 0;
}

// ---------------- router: logits -> softmax -> top2 -> renorm -> lists ----------------
__global__ void router_kernel(const float* __restrict__ x, const float* __restrict__ wg) {
    int warp = (blockIdx.x * blockDim.x + threadIdx.x) >> 5;
    int lane = threadIdx.x & 31;
    if (warp >= M_TOK) return;
    const float* xr = x + (long long)warp * H_DIM;
    float acc[E_NUM];
#pragma unroll
    for (int e = 0; e < E_NUM; e++) acc[e] = 0.f;
    for (int h = lane; h < H_DIM; h += 32) {
        float xv = xr[h];
        const float4* wr = (const float4*)(wg + (long long)h * E_NUM);
        float4 w0 = wr[0], w1 = wr[1];
        acc[0] += xv * w0.x; acc[1] += xv * w0.y; acc[2] += xv * w0.z; acc[3] += xv * w0.w;
        acc[4] += xv * w1.x; acc[5] += xv * w1.y; acc[6] += xv * w1.z; acc[7] += xv * w1.w;
    }
#pragma unroll
    for (int e = 0; e < E_NUM; e++)
#pragma unroll
        for (int o = 16; o > 0; o >>= 1)
            acc[e] += __shfl_xor_sync(0xffffffffu, acc[e], o);
    if (lane == 0) {
        float mx = acc[0];
#pragma unroll
        for (int e = 1; e < E_NUM; e++) mx = fmaxf(mx, acc[e]);
        float p[E_NUM];
#pragma unroll
        for (int e = 0; e < E_NUM; e++) p[e] = expf(acc[e] - mx);
        int i0 = 0;
#pragma unroll
        for (int e = 1; e < E_NUM; e++) if (p[e] > p[i0]) i0 = e;
        int i1 = (i0 == 0) ? 1 : 0;
#pragma unroll
        for (int e = 0; e < E_NUM; e++) { if (e == i0 || e == i1) continue; if (p[e] > p[i1]) i1 = e; }
        float denom = p[i0] + p[i1];
        int m = warp;
        g_pw[2 * m + 0] = p[i0] / denom;
        g_pw[2 * m + 1] = p[i1] / denom;
        int s0 = atomicAdd(&g_cnt[i0], 1); g_list[i0 * M_TOK + s0] = 2 * m + 0;
        int s1 = atomicAdd(&g_cnt[i1], 1); g_list[i1 * M_TOK + s1] = 2 * m + 1;
    }
}

// ---------------- grouped GEMM (fp16 mma.sync m16n8k16, fp32 accum) ----------------
// MODE 1: A = x (row = pair>>1), W = w1[e] (K=H, N=2I), C = g_gu (row = pair)
// MODE 2: A = g_h (row = pair),  W = w2[e] (K=I, N=H),  C = g_dn (row = pair)
// fp32 gmem -> regs -> cvt fp16 -> smem (converted exactly once per element),
// ldmatrix fragment loads, LDG prefetched 2 stages ahead.
template<int MODE, int KDIM>
__global__ void __launch_bounds__(256, 1) gemm_f16_kernel(
    const float* __restrict__ Aext, const float* __restrict__ Wbase,
    int N, int ldA, int ldC)
{
    constexpr int nK = KDIM / BK;
    const float* Asrc = (MODE == 1) ? Aext : (const float*)g_h;
    float* C = (MODE == 1) ? g_gu : g_dn;

    int e = blockIdx.z;
    int cnt = g_cnt[e];
    int row0 = blockIdx.x * BM;
    if (row0 >= cnt) return;
    int n0 = blockIdx.y * BN;
    const float* W = Wbase + (size_t)e * KDIM * N;

    __shared__ __half As[2][BM * LDA];
    __shared__ __half Bs[2][BK * LDB];

    int tid = threadIdx.x;

    // ---- global load assignment ----
    // A: 128 rows x 32 floats; thread t handles row t>>1, half (t&1)*16 floats
    int ar = tid >> 1, ah = tid & 1;
    int gr = row0 + ar;
    int srow = 0;
    if (gr < cnt) {
        int p = g_list[e * M_TOK + gr];
        srow = (MODE == 1) ? (p >> 1) : p;
    }
    const float* aG = Asrc + (size_t)srow * ldA + ah * 16;
    __half* aSts0 = &As[0][ar * LDA + ah * 16];

    // B: 32 rows x 128 floats; thread t handles row t>>3, seg (t&7)*16 floats
    int br = tid >> 3, bseg = tid & 7;
    const float* bG = W + (size_t)br * N + n0 + bseg * 16;
    __half* bSts0 = &Bs[0][br * LDB + bseg * 16];

    // ---- prefetch stages 0 and 1 into registers ----
    float4 ra[2][4], rb[2][4];
#pragma unroll
    for (int s = 0; s < 2; s++) {
#pragma unroll
        for (int j = 0; j < 4; j++) ra[s][j] = *(const float4*)(aG + s * BK + j * 4);
#pragma unroll
        for (int j = 0; j < 4; j++) rb[s][j] = *(const float4*)(bG + (size_t)(s * BK) * N + j * 4);
    }

    float c[4][4][4];
#pragma unroll
    for (int i = 0; i < 4; i++)
#pragma unroll
        for (int j = 0; j < 4; j++)
#pragma unroll
            for (int k = 0; k < 4; k++) c[i][j][k] = 0.f;

    int lane = tid & 31, warp = tid >> 5;
    int wm = warp >> 2, wn = warp & 3;   // 2 m-warps x 4 n-warps; warp tile 64x32
    int g = lane >> 2, t = lane & 3;

    // ldmatrix base addresses (stage 0)
    uint32_t aF = sptr(&As[0][(wm * 64 + (lane & 15)) * LDA + (lane >> 4) * 8]);
    uint32_t bF = sptr(&Bs[0][((lane & 7) + ((lane >> 3) & 1) * 8) * LDB + wn * 32]);
    const uint32_t stA = BM * LDA * 2;   // bytes per A stage
    const uint32_t stB = BK * LDB * 2;   // bytes per B stage

#pragma unroll 2
    for (int kt = 0; kt < nK; kt++) {
        int s = kt & 1;

        // ---- convert + store this stage's registers to fp16 smem ----
        {
            __half* ad = aSts0 + s * (BM * LDA);
            uint4 v0, v1;
            v0.x = pack2(ra[s][0].x, ra[s][0].y); v0.y = pack2(ra[s][0].z, ra[s][0].w);
            v0.z = pack2(ra[s][1].x, ra[s][1].y); v0.w = pack2(ra[s][1].z, ra[s][1].w);
            v1.x = pack2(ra[s][2].x, ra[s][2].y); v1.y = pack2(ra[s][2].z, ra[s][2].w);
            v1.z = pack2(ra[s][3].x, ra[s][3].y); v1.w = pack2(ra[s][3].z, ra[s][3].w);
            *(uint4*)(ad) = v0;
            *(uint4*)(ad + 8) = v1;

            __half* bd = bSts0 + s * (BK * LDB);
            uint4 w0, w1;
            w0.x = pack2(rb[s][0].x, rb[s][0].y); w0.y = pack2(rb[s][0].z, rb[s][0].w);
            w0.z = pack2(rb[s][1].x, rb[s][1].y); w0.w = pack2(rb[s][1].z, rb[s][1].w);
            w1.x = pack2(rb[s][2].x, rb[s][2].y); w1.y = pack2(rb[s][2].z, rb[s][2].w);
            w1.z = pack2(rb[s][3].x, rb[s][3].y); w1.w = pack2(rb[s][3].z, rb[s][3].w);
            *(uint4*)(bd) = w0;
            *(uint4*)(bd + 8) = w1;
        }
        __syncthreads();

        // ---- prefetch stage kt+2 (2 stages ahead: ~2 iterations of latency cover) ----
        if (kt + 2 < nK) {
#pragma unroll
            for (int j = 0; j < 4; j++) ra[s][j] = *(const float4*)(aG + (kt + 2) * BK + j * 4);
#pragma unroll
            for (int j = 0; j < 4; j++) rb[s][j] = *(const float4*)(bG + (size_t)((kt + 2) * BK) * N + j * 4);
        }

        // ---- compute from fp16 smem ----
#pragma unroll
        for (int kk = 0; kk < BK; kk += 16) {
            uint32_t af[4][4];
#pragma unroll
            for (int mi = 0; mi < 4; mi++) {
                uint32_t addr = aF + s * stA + (uint32_t)(mi * 16 * LDA + kk) * 2;
                asm volatile("ldmatrix.sync.aligned.m8n8.x4.shared.b16 {%0,%1,%2,%3}, [%4];"
                    : "=r"(af[mi][0]), "=r"(af[mi][1]), "=r"(af[mi][2]), "=r"(af[mi][3])
                    : "r"(addr));
            }
            uint32_t bf[4][2];
#pragma unroll
            for (int ni = 0; ni < 4; ni++) {
                uint32_t addr = bF + s * stB + (uint32_t)(kk * LDB + ni * 8) * 2;
                asm volatile("ldmatrix.sync.aligned.m8n8.x2.trans.shared.b16 {%0,%1}, [%2];"
                    : "=r"(bf[ni][0]), "=r"(bf[ni][1])
                    : "r"(addr));
            }
#pragma unroll
            for (int mi = 0; mi < 4; mi++)
#pragma unroll
                for (int ni = 0; ni < 4; ni++)
                    mma16816(c[mi][ni], af[mi], bf[ni]);
        }
    }

    // ---- writeback (skip padded rows) ----
#pragma unroll
    for (int mi = 0; mi < 4; mi++) {
#pragma unroll
        for (int half = 0; half < 2; half++) {
            int r = wm * 64 + mi * 16 + g + half * 8;
            int grr = row0 + r;
            if (grr < cnt) {
                int p = g_list[e * M_TOK + grr];
                float* dst = C + (size_t)p * ldC + n0;
#pragma unroll
                for (int ni = 0; ni < 4; ni++) {
                    float2 v;
                    v.x = c[mi][ni][half * 2 + 0];
                    v.y = c[mi][ni][half * 2 + 1];
                    *(float2*)(dst + wn * 32 + ni * 8 + 2 * t) = v;
                }
            }
        }
    }
}

// ---------------- silu(g) * u ----------------
__global__ void silu_mul_kernel() {
    const int I4 = I_DIM / 4;
    long long idx = (long long)blockIdx.x * blockDim.x + threadIdx.x; // exactly P_NUM*I4 threads
    long long p = idx / I4;
    int i4 = (int)(idx % I4);
    const float* gp = g_gu + p * (2 * I_DIM);
    float4 gv = *(const float4*)(gp + i4 * 4);
    float4 uv = *(const float4*)(gp + I_DIM + i4 * 4);
    float4 h;
    h.x = gv.x / (1.f + expf(-gv.x)) * uv.x;
    h.y = gv.y / (1.f + expf(-gv.y)) * uv.y;
    h.z = gv.z / (1.f + expf(-gv.z)) * uv.z;
    h.w = gv.w / (1.f + expf(-gv.w)) * uv.w;
    *(float4*)(g_h + p * I_DIM + i4 * 4) = h;
}

// ---------------- combine: out[m] = w0*down[2m] + w1*down[2m+1] ----------------
__global__ void combine_kernel(float* __restrict__ out) {
    const int H4 = H_DIM / 4;
    int idx = blockIdx.x * blockDim.x + threadIdx.x;  // exactly M_TOK*H4 threads
    int m = idx / H4;
    int h4 = idx % H4;
    float w0 = g_pw[2 * m + 0];
    float w1 = g_pw[2 * m + 1];
    float4 d0 = *(const float4*)(g_dn + (long long)(2 * m + 0) * H_DIM + h4 * 4);
    float4 d1 = *(const float4*)(g_dn + (long long)(2 * m + 1) * H_DIM + h4 * 4);
    float4 o;
    o.x = w0 * d0.x + w1 * d1.x;
    o.y = w0 * d0.y + w1 * d1.y;
    o.z = w0 * d0.z + w1 * d1.z;
    o.w = w0 * d0.w + w1 * d1.w;
    *(float4*)(out + (long long)m * H_DIM + h4 * 4) = o;
}

// ---------------- launcher ----------------
extern "C" void kernel_launch(void* const* d_in, const int* in_sizes, int n_in,
                              void* d_out, int out_size) {
    const float* x  = (const float*)d_in[0];   // [1,512,2048]
    const float* wg = (const float*)d_in[1];   // [2048,8]
    const float* w1 = (const float*)d_in[2];   // [8,2048,11264]
    const float* w2 = (const float*)d_in[3];   // [8,5632,2048]
    float* out = (float*)d_out;                // [1,512,2048]
    (void)in_sizes; (void)n_in; (void)out_size;

    reset_kernel<<<1, 32>>>();
    router_kernel<<<M_TOK / 8, 256>>>(x, wg);  // 1 warp / token

    dim3 grid1(M_TOK / BM, (2 * I_DIM) / BN, E_NUM);  // (4, 88, 8)
    gemm_f16_kernel<1, H_DIM><<<grid1, 256>>>(x, w1, 2 * I_DIM, H_DIM, 2 * I_DIM);

    silu_mul_kernel<<<(P_NUM * (I_DIM / 4)) / 256, 256>>>();  // 5632 blocks, exact cover

    dim3 grid2(M_TOK / BM, H_DIM / BN, E_NUM);        // (4, 16, 8)
    gemm_f16_kernel<2, I_DIM><<<grid2, 256>>>(x /*unused*/, w2, H_DIM, I_DIM, H_DIM);

    combine_kernel<<<(M_TOK * (H_DIM / 4)) / 256, 256>>>(out);
}